// round 2
// baseline (speedup 1.0000x reference)
#include <cuda_runtime.h>
#include <cstdint>

// LocalAtten: NB=4, NLOC=2048, NNEI=64, NI=ND=64, NH=4
// Algebraic refactor:
//   P[h]  (64x64) = Wq_h @ Wkv_k_h^T / sqrt(ND)   -> s[j,h] = g1 . P_h . gg1_j
//   M[h]  (64x64) = Wkv_v_h @ Wh_h                -> out = sum_h u_h @ M_h + bh
// where u_h = sum_j softmax-weight[j,h] * gg1_j.
// Removes per-neighbor K/V projections (33x FLOP reduction); kernel is
// HBM-bound on gg1. Masked neighbor rows are never loaded.
// R2 fix: nlist_mask arrives as int32 (bool promoted by harness), not bytes.

__device__ float d_P[4 * 64 * 64];  // [h][ip][i]
__device__ float d_M[4 * 64 * 64];  // [h][i][o]

// ---------------------------------------------------------------------------
// Precompute kernel: grid (4 heads, 2 matrices), 256 threads.
// ---------------------------------------------------------------------------
__global__ __launch_bounds__(256) void la_precompute(
    const float* __restrict__ Wq,   // (64, 256)  col = d*4 + h
    const float* __restrict__ Wkv,  // (64, 512)  col = d*8 + c, c<4 -> K_h, c>=4 -> V_h
    const float* __restrict__ Wh)   // (256, 64)  row = h*64 + d
{
    int h = blockIdx.x;
    int mat = blockIdx.y;
    int t = threadIdx.x;
    __shared__ float A[64][65];
    __shared__ float B[64][65];

    if (mat == 0) {
        // A[ip][d] = Wq[ip, d*4+h];  B[i][d] = Wkv[i, d*8+h]
        for (int e = t; e < 4096; e += 256) {
            int r = e >> 6, d = e & 63;
            A[r][d] = Wq[r * 256 + d * 4 + h];
            B[r][d] = Wkv[r * 512 + d * 8 + h];
        }
        __syncthreads();
        // P[h][ip][i] = (1/8) * sum_d A[ip][d]*B[i][d]
        for (int e = t; e < 4096; e += 256) {
            int ip = e >> 6, i = e & 63;
            float acc = 0.f;
#pragma unroll 8
            for (int d = 0; d < 64; d++) acc += A[ip][d] * B[i][d];
            d_P[(h * 64 + ip) * 64 + i] = acc * 0.125f;  // 1/sqrt(64)
        }
    } else {
        // A[i][d] = Wkv[i, d*8+4+h];  B[d][o] = Wh[h*64+d, o]
        for (int e = t; e < 4096; e += 256) {
            int r = e >> 6, c = e & 63;
            A[r][c] = Wkv[r * 512 + c * 8 + 4 + h];
            B[r][c] = Wh[(h * 64 + r) * 64 + c];
        }
        __syncthreads();
        // M[h][i][o] = sum_d A[i][d]*B[d][o]
        for (int e = t; e < 4096; e += 256) {
            int i = e >> 6, o = e & 63;
            float acc = 0.f;
#pragma unroll 8
            for (int d = 0; d < 64; d++) acc += A[i][d] * B[d][o];
            d_M[(h * 64 + i) * 64 + o] = acc;
        }
    }
}

// ---------------------------------------------------------------------------
// Main fused kernel: one CTA per (b,l) = 8192 CTAs, 256 threads.
// ---------------------------------------------------------------------------
__global__ __launch_bounds__(256) void la_main(
    const float* __restrict__ g1,          // (8192, 64)
    const float* __restrict__ gg1,         // (8192, 64, 64)
    const int* __restrict__ msk,           // (8192, 64) bool promoted to int32
    const float* __restrict__ bh,          // (64,)
    float* __restrict__ out)               // (8192, 64)
{
    int bl = blockIdx.x;
    int t = threadIdx.x;

    __shared__ float ggT[64][65];   // transposed compacted gg1 rows: [i][j]
    __shared__ float w[4][64];      // w_h, later reused for u_h
    __shared__ float aw[64][5];     // logits -> attention weights [j][h]
    __shared__ float g1row[64];
    __shared__ int idxs[64];
    __shared__ int mcount_s;
    __shared__ float pout[4][64];

    if (t < 64) g1row[t] = g1[bl * 64 + t];

    // Ordered, deterministic mask compaction (warp 0).
    if (t < 32) {
        int base = 0;
#pragma unroll
        for (int c = 0; c < 2; c++) {
            int j = c * 32 + t;
            bool bit = msk[bl * 64 + j] != 0;
            unsigned bal = __ballot_sync(0xffffffffu, bit);
            int pos = base + __popc(bal & ((1u << t) - 1u));
            if (bit) idxs[pos] = j;
            base += __popc(bal);
        }
        if (t == 0) mcount_s = base;
    }
    __syncthreads();
    int m = mcount_s;

    // Load only unmasked gg1 rows, transposed into ggT[i][j] (pad 65: both
    // later read phases are bank-conflict-free).
    const float* ggbase = gg1 + (size_t)bl * 64 * 64;
    for (int e = t; e < m * 16; e += 256) {
        int jj = e >> 4, qq = e & 15;
        float4 v = *(const float4*)(ggbase + idxs[jj] * 64 + qq * 4);
        int d = qq * 4;
        ggT[d + 0][jj] = v.x;
        ggT[d + 1][jj] = v.y;
        ggT[d + 2][jj] = v.z;
        ggT[d + 3][jj] = v.w;
    }

    // w[h][i] = sum_ip g1row[ip] * P[h][ip][i]   (P L1/L2-hot, coalesced over i)
    {
        int h = t >> 6, i = t & 63;
        const float* Pp = d_P + h * 4096 + i;
        float acc = 0.f;
#pragma unroll 8
        for (int ip = 0; ip < 64; ip++) acc += g1row[ip] * Pp[ip * 64];
        w[h][i] = acc;
    }
    __syncthreads();

    // logits s[j,h] = sum_i ggT[i][j] * w[h][i]
    {
        int h = t >> 6, j = t & 63;
        if (j < m) {
            float acc = 0.f;
#pragma unroll 8
            for (int i = 0; i < 64; i++) acc += ggT[i][j] * w[h][i];
            aw[j][h] = acc;
        }
    }
    __syncthreads();

    // softmax over compacted j, one warp per head
    if (t < 128) {
        int h = t >> 5, lane = t & 31;
        float x0 = (lane < m) ? aw[lane][h] : -1e30f;
        float x1 = (lane + 32 < m) ? aw[lane + 32][h] : -1e30f;
        float mx = fmaxf(x0, x1);
#pragma unroll
        for (int off = 16; off; off >>= 1)
            mx = fmaxf(mx, __shfl_xor_sync(0xffffffffu, mx, off));
        float e0 = (lane < m) ? __expf(x0 - mx) : 0.f;
        float e1 = (lane + 32 < m) ? __expf(x1 - mx) : 0.f;
        float s = e0 + e1;
#pragma unroll
        for (int off = 16; off; off >>= 1)
            s += __shfl_xor_sync(0xffffffffu, s, off);
        float inv = (s > 0.f) ? 1.f / s : 0.f;
        if (lane < m) aw[lane][h] = e0 * inv;
        if (lane + 32 < m) aw[lane + 32][h] = e1 * inv;
    }
    __syncthreads();

    // u[h][i] = sum_j aw[j][h] * ggT[i][j]   (overwrite w; all reads done)
    {
        int h = t >> 6, i = t & 63;
        float acc = 0.f;
#pragma unroll 4
        for (int j = 0; j < m; j++) acc += aw[j][h] * ggT[i][j];
        w[h][i] = acc;
    }
    __syncthreads();

    // out[o] = bh[o] + sum_h sum_i u[h][i] * M[h][i][o]
    {
        int h = t >> 6, o = t & 63;
        const float* Mp = d_M + h * 4096 + o;
        float acc = 0.f;
#pragma unroll 8
        for (int i = 0; i < 64; i++) acc += w[h][i] * Mp[i * 64];
        pout[h][o] = acc;
    }
    __syncthreads();

    if (t < 64)
        out[bl * 64 + t] =
            bh[t] + pout[0][t] + pout[1][t] + pout[2][t] + pout[3][t];
}

// ---------------------------------------------------------------------------
extern "C" void kernel_launch(void* const* d_in, const int* in_sizes, int n_in,
                              void* d_out, int out_size)
{
    const float* g1 = (const float*)d_in[0];
    const float* gg1 = (const float*)d_in[1];
    const int* msk = (const int*)d_in[2];
    const float* Wq = (const float*)d_in[3];
    const float* Wkv = (const float*)d_in[4];
    const float* Wh = (const float*)d_in[5];
    const float* bh = (const float*)d_in[6];
    float* out = (float*)d_out;

    la_precompute<<<dim3(4, 2), 256>>>(Wq, Wkv, Wh);
    la_main<<<8192, 256>>>(g1, gg1, msk, bh, out);
}

// round 5
// speedup vs baseline: 1.3878x; 1.3878x over previous
#include <cuda_runtime.h>
#include <cstdint>

// LocalAtten: NB=4, NLOC=2048, NNEI=64, NI=ND=64, NH=4
//   P[h] = Wq_h @ Wkv_k_h^T / 8   -> s[j,h] = g1 . P_h . gg1_j
//   M[h] = Wkv_v_h @ Wh_h         -> out = sum_h u_h @ M_h + bh
// R3: L1-wavefront-bound per ncu (L1=79%, DRAM=9%). Changes:
//  - T=4 locs per CTA: P/M (128KB) streamed once per CTA, reused x4.
//  - XOR-swizzled (q ^ (j&15)) float4 gg tile: conflict-free STS.128,
//    float4 row reads (logits) AND scalar column reads (u) simultaneously.
//  - logits/u threads compute all 4 heads per gg element (W / aw become
//    float4 broadcasts) -> gg smem read once per phase instead of 4x.

__device__ float d_P[4 * 64 * 64];  // [h][ip][i]
__device__ float d_M[4 * 64 * 64];  // [h][i][o]

#define T 4

// ---------------------------------------------------------------------------
__global__ __launch_bounds__(256) void la_precompute(
    const float* __restrict__ Wq,   // (64, 256)  col = d*4 + h
    const float* __restrict__ Wkv,  // (64, 512)  col = d*8 + c
    const float* __restrict__ Wh)   // (256, 64)  row = h*64 + d
{
    int h = blockIdx.x;
    int mat = blockIdx.y;
    int t = threadIdx.x;
    __shared__ float A[64][65];
    __shared__ float B[64][65];

    if (mat == 0) {
        for (int e = t; e < 4096; e += 256) {
            int r = e >> 6, d = e & 63;
            A[r][d] = Wq[r * 256 + d * 4 + h];
            B[r][d] = Wkv[r * 512 + d * 8 + h];
        }
        __syncthreads();
        for (int e = t; e < 4096; e += 256) {
            int ip = e >> 6, i = e & 63;
            float acc = 0.f;
#pragma unroll 8
            for (int d = 0; d < 64; d++) acc += A[ip][d] * B[i][d];
            d_P[(h * 64 + ip) * 64 + i] = acc * 0.125f;
        }
    } else {
        for (int e = t; e < 4096; e += 256) {
            int r = e >> 6, c = e & 63;
            A[r][c] = Wkv[r * 512 + c * 8 + 4 + h];
            B[r][c] = Wh[(h * 64 + r) * 64 + c];
        }
        __syncthreads();
        for (int e = t; e < 4096; e += 256) {
            int i = e >> 6, o = e & 63;
            float acc = 0.f;
#pragma unroll 8
            for (int d = 0; d < 64; d++) acc += A[i][d] * B[d][o];
            d_M[(h * 64 + i) * 64 + o] = acc;
        }
    }
}

// ---------------------------------------------------------------------------
// Main kernel: one CTA per 4 locs. 2048 CTAs x 256 threads.
// ---------------------------------------------------------------------------
__global__ __launch_bounds__(256) void la_main(
    const float* __restrict__ g1,   // (8192, 64)
    const float* __restrict__ gg1,  // (8192, 64, 64)
    const int* __restrict__ msk,    // (8192, 64) int32 bool
    const float* __restrict__ bh,   // (64,)
    float* __restrict__ out)        // (8192, 64)
{
    __shared__ __align__(16) float4 ggS[64 * 16];   // swizzled rows, 16KB
    __shared__ __align__(16) float  Wl[T][256];     // [l][h*64+i]
    __shared__ __align__(16) float4 g1T[64];        // [ip] components = l
    __shared__ __align__(16) float  uT[256 * T];    // [(h*64+i)*4 + l]
    __shared__ __align__(16) float4 aw4[64];        // [j] components = h
    __shared__ __align__(16) float4 part[128];      // scratch [idx*2+half]
    __shared__ __align__(16) float4 pout[4][64];    // [h][o] components = l
    __shared__ int idxs[T][64];
    __shared__ int mcnt[T];

    int g = blockIdx.x;
    int t = threadIdx.x;
    int lane = t & 31, wid = t >> 5;

    // --- mask compaction, one warp per loc ---
    if (wid < T) {
        const int* mp = msk + (size_t)(g * T + wid) * 64;
        int base = 0;
#pragma unroll
        for (int c = 0; c < 2; c++) {
            int j = c * 32 + lane;
            bool bit = mp[j] != 0;
            unsigned bal = __ballot_sync(0xffffffffu, bit);
            int pos = base + __popc(bal & ((1u << lane) - 1u));
            if (bit) idxs[wid][pos] = j;
            base += __popc(bal);
        }
        if (lane == 0) mcnt[wid] = base;
    }
    // --- g1 transposed staging: g1T[ip].l = g1[loc l][ip] ---
    {
        int l = t >> 6, ip = t & 63;
        ((float*)g1T)[ip * 4 + l] = g1[(size_t)(g * T + l) * 64 + ip];
    }
    __syncthreads();

    // --- W phase (batched over T): Wl[l][h*64+i] = sum_ip g1[l][ip]*P[h][ip][i]
    {
        int h = t >> 6, i = t & 63;
        float a0 = 0.f, a1 = 0.f, a2 = 0.f, a3 = 0.f;
        const float* Pp = d_P + h * 4096 + i;
#pragma unroll 8
        for (int ip = 0; ip < 64; ip++) {
            float p = Pp[ip * 64];
            float4 gv = g1T[ip];
            a0 += gv.x * p; a1 += gv.y * p; a2 += gv.z * p; a3 += gv.w * p;
        }
        Wl[0][h * 64 + i] = a0;
        Wl[1][h * 64 + i] = a1;
        Wl[2][h * 64 + i] = a2;
        Wl[3][h * 64 + i] = a3;
    }

    // --- per-loc attention ---
    for (int l = 0; l < T; l++) {
        int m = mcnt[l];

        // gather unmasked rows into swizzled tile (slot = q ^ (j&15))
        const float* ggb = gg1 + (size_t)(g * T + l) * 4096;
        for (int e = t; e < m * 16; e += 256) {
            int jj = e >> 4, qq = e & 15;
            float4 v = *(const float4*)(ggb + idxs[l][jj] * 64 + qq * 4);
            ggS[jj * 16 + (qq ^ (jj & 15))] = v;
        }
        __syncthreads();  // also orders Wl writes (first iter)

        // logits: thread (half,j) computes 4 heads over its 32 i's
        if (t < 128) {
            int half = t >> 6, j = t & 63;
            int jx = j & 15;
            float s0 = 0.f, s1 = 0.f, s2 = 0.f, s3 = 0.f;
            const float4* wb = (const float4*)Wl[l];
#pragma unroll
            for (int qq = 0; qq < 8; qq++) {
                int q = half * 8 + qq;
                float4 gv = ggS[j * 16 + (q ^ jx)];
                float4 w0 = wb[q];
                float4 w1 = wb[16 + q];
                float4 w2 = wb[32 + q];
                float4 w3 = wb[48 + q];
                s0 += gv.x * w0.x + gv.y * w0.y + gv.z * w0.z + gv.w * w0.w;
                s1 += gv.x * w1.x + gv.y * w1.y + gv.z * w1.z + gv.w * w1.w;
                s2 += gv.x * w2.x + gv.y * w2.y + gv.z * w2.z + gv.w * w2.w;
                s3 += gv.x * w3.x + gv.y * w3.y + gv.z * w3.z + gv.w * w3.w;
            }
            part[j * 2 + half] = make_float4(s0, s1, s2, s3);
        }
        __syncthreads();
        if (t < 64) {
            int j = t;
            float4 a = part[j * 2], b = part[j * 2 + 1];
            float4 s = make_float4(a.x + b.x, a.y + b.y, a.z + b.z, a.w + b.w);
            if (j >= m) s = make_float4(-1e30f, -1e30f, -1e30f, -1e30f);
            aw4[j] = s;
        }
        __syncthreads();

        // softmax: warp per head over 64 compacted j
        if (t < 128) {
            int h = t >> 5, ln = t & 31;
            const float* af = (const float*)aw4;
            float x0 = af[ln * 4 + h];
            float x1 = af[(ln + 32) * 4 + h];
            float mx = fmaxf(x0, x1);
#pragma unroll
            for (int off = 16; off; off >>= 1)
                mx = fmaxf(mx, __shfl_xor_sync(0xffffffffu, mx, off));
            float e0 = __expf(x0 - mx);
            float e1 = __expf(x1 - mx);
            float s = e0 + e1;
#pragma unroll
            for (int off = 16; off; off >>= 1)
                s += __shfl_xor_sync(0xffffffffu, s, off);
            float inv = 1.f / s;
            ((float*)aw4)[ln * 4 + h] = e0 * inv;
            ((float*)aw4)[(ln + 32) * 4 + h] = e1 * inv;
        }
        __syncthreads();

        // u: thread (half,i) computes 4 heads over its j-range
        if (t < 128) {
            int half = t >> 6, i = t & 63;
            int mh = (m + 1) >> 1;
            int j0 = half ? mh : 0, j1 = half ? m : mh;
            int ihi = i >> 2, ilo = i & 3;
            float u0 = 0.f, u1 = 0.f, u2 = 0.f, u3 = 0.f;
            const float* ggf = (const float*)ggS;
            for (int j = j0; j < j1; j++) {
                float4 a = aw4[j];
                float v = ggf[j * 64 + ((ihi ^ (j & 15)) << 2) + ilo];
                u0 += a.x * v; u1 += a.y * v; u2 += a.z * v; u3 += a.w * v;
            }
            part[i * 2 + half] = make_float4(u0, u1, u2, u3);
        }
        __syncthreads();
        if (t < 64) {
            int i = t;
            float4 a = part[i * 2], b = part[i * 2 + 1];
            uT[(0 * 64 + i) * 4 + l] = a.x + b.x;
            uT[(1 * 64 + i) * 4 + l] = a.y + b.y;
            uT[(2 * 64 + i) * 4 + l] = a.z + b.z;
            uT[(3 * 64 + i) * 4 + l] = a.w + b.w;
        }
        __syncthreads();  // ggS free for next loc
    }

    // --- out phase (batched over T): out[l][o] = bh + sum_h,i u[l][h][i]*M[h][i][o]
    {
        int h = t >> 6, o = t & 63;
        float a0 = 0.f, a1 = 0.f, a2 = 0.f, a3 = 0.f;
        const float* Mp = d_M + h * 4096 + o;
        const float4* ub = (const float4*)uT + h * 64;
#pragma unroll 8
        for (int i = 0; i < 64; i++) {
            float mv = Mp[i * 64];
            float4 uv = ub[i];
            a0 += uv.x * mv; a1 += uv.y * mv; a2 += uv.z * mv; a3 += uv.w * mv;
        }
        pout[h][o] = make_float4(a0, a1, a2, a3);
    }
    __syncthreads();
    if (t < 64) {
        int o = t;
        float4 r0 = pout[0][o], r1 = pout[1][o], r2 = pout[2][o], r3 = pout[3][o];
        float b = bh[o];
        out[(size_t)(g * T + 0) * 64 + o] = r0.x + r1.x + r2.x + r3.x + b;
        out[(size_t)(g * T + 1) * 64 + o] = r0.y + r1.y + r2.y + r3.y + b;
        out[(size_t)(g * T + 2) * 64 + o] = r0.z + r1.z + r2.z + r3.z + b;
        out[(size_t)(g * T + 3) * 64 + o] = r0.w + r1.w + r2.w + r3.w + b;
    }
}

// ---------------------------------------------------------------------------
extern "C" void kernel_launch(void* const* d_in, const int* in_sizes, int n_in,
                              void* d_out, int out_size)
{
    const float* g1 = (const float*)d_in[0];
    const float* gg1 = (const float*)d_in[1];
    const int* msk = (const int*)d_in[2];
    const float* Wq = (const float*)d_in[3];
    const float* Wkv = (const float*)d_in[4];
    const float* Wh = (const float*)d_in[5];
    const float* bh = (const float*)d_in[6];
    float* out = (float*)d_out;

    la_precompute<<<dim3(4, 2), 256>>>(Wq, Wkv, Wh);
    la_main<<<2048, 256>>>(g1, gg1, msk, bh, out);
}